// round 9
// baseline (speedup 1.0000x reference)
#include <cuda_runtime.h>
#include <cstdint>

// Problem constants (B=64, C=512, H=W=28, G=8)
#define HWN    784
#define HW4    196
#define CPG    64
#define EPS    1e-5f
#define NTHR   512
#define NW     16
#define SLICE  49          // HWN / 16 warps
#define NTILE  512
#define GRID   148

#define CCH          4                    // channels per chunk
#define NCHUNK       16
#define CHUNK_FLOATS (CCH * HWN)          // 3136
#define CHUNK_BYTES  (CHUNK_FLOATS * 4)   // 12544
#define TILE_FLOATS  (CPG * HWN)          // 50176

// smem layout (floats)
#define OFF_S      TILE_FLOATS            // s / gate buffer (784)
#define OFF_MEANS  (OFF_S + HWN)          // 64 channel means
#define OFF_RED    (OFF_MEANS + CPG)      // 34 scratch
#define OFF_MBAR   (OFF_RED + 36)         // 16 x u64 (even float offset -> 8B aligned)
#define SMEM_FLOATS (OFF_MBAR + 32)
#define SMEM_BYTES  (SMEM_FLOATS * 4)     // ~204.4 KB

__device__ __forceinline__ uint32_t smem_u32(const void* p) {
    uint32_t a;
    asm("{ .reg .u64 t; cvta.to.shared.u64 t, %1; cvt.u32.u64 %0, t; }"
        : "=r"(a) : "l"(p));
    return a;
}

__device__ __forceinline__ void mbar_wait(uint32_t mbar, uint32_t parity) {
    asm volatile(
        "{\n\t"
        ".reg .pred P;\n\t"
        "WL_%=: mbarrier.try_wait.parity.acquire.cta.shared::cta.b64 P, [%0], %1, 0x989680;\n\t"
        "@P bra WD_%=;\n\t"
        "bra WL_%=;\n\t"
        "WD_%=:\n\t"
        "}" :: "r"(mbar), "r"(parity) : "memory");
}

__device__ __forceinline__ void tma_load_chunk(uint32_t mbar, uint32_t dst,
                                               const char* src) {
    asm volatile("mbarrier.arrive.expect_tx.shared::cta.b64 _, [%0], %1;"
                 :: "r"(mbar), "r"((uint32_t)CHUNK_BYTES) : "memory");
    asm volatile(
        "cp.async.bulk.shared::cluster.global.mbarrier::complete_tx::bytes "
        "[%0], [%1], %2, [%3];"
        :: "r"(dst), "l"(src), "r"((uint32_t)CHUNK_BYTES), "r"(mbar)
        : "memory");
}

__device__ __forceinline__ void tma_store_chunk(char* dstg, uint32_t src) {
    asm volatile(
        "cp.async.bulk.global.shared::cta.bulk_group [%0], [%1], %2;"
        :: "l"(dstg), "r"(src), "r"((uint32_t)CHUNK_BYTES) : "memory");
    asm volatile("cp.async.bulk.commit_group;" ::: "memory");
}

__global__ __launch_bounds__(NTHR, 1)
void simam_persist_kernel(const float* __restrict__ x,
                          const float* __restrict__ weight,
                          const float* __restrict__ bias,
                          float* __restrict__ out)
{
    extern __shared__ float smem[];
    float*  s_s     = smem + OFF_S;
    float4* s_s4    = (float4*)s_s;
    float*  s_means = smem + OFF_MEANS;
    float*  s_red   = smem + OFF_RED;
    const uint32_t mbar0 = smem_u32(smem + OFF_MBAR);
    const uint32_t sx0   = smem_u32(smem);

    const int tid  = threadIdx.x;
    const int w    = tid >> 5;
    const int lane = tid & 31;

    // phase-2 multiply indices (constant across chunks/tiles)
    const int j1   = tid;                        // float4 idx in chunk (784 total)
    const int hw1  = j1 % HW4;
    const int j2   = tid + NTHR;
    const int hw2  = j2 % HW4;
    const bool p2b = (j2 < CCH * HW4);

    // ---- init barriers, prologue load of first tile ----
    if (tid == 0) {
        #pragma unroll
        for (int i = 0; i < NCHUNK; i++)
            asm volatile("mbarrier.init.shared::cta.b64 [%0], 1;"
                         :: "r"(mbar0 + i * 8) : "memory");
    }
    __syncthreads();
    {
        int t0 = blockIdx.x;
        if (tid == 0 && t0 < NTILE) {
            const char* xt = (const char*)(x + (size_t)t0 * TILE_FLOATS);
            #pragma unroll
            for (int c = 0; c < NCHUNK; c++)
                tma_load_chunk(mbar0 + c * 8, sx0 + c * CHUNK_BYTES,
                               xt + c * CHUNK_BYTES);
        }
    }

    int it = 0;
    for (int tile = blockIdx.x; tile < NTILE; tile += GRID, ++it) {
        const uint32_t par = (uint32_t)(it & 1);
        const int g = tile & 7;
        float* ot = out + (size_t)tile * TILE_FLOATS;

        // ================= Phase 1: means + s accumulation =================
        float acc0 = 0.f, acc1 = 0.f;
        for (int c = 0; c < NCHUNK; c++) {
            mbar_wait(mbar0 + c * 8, par);
            float* buf = smem + c * CHUNK_FLOATS;

            if (w < CCH) {                        // warps 0..3: channel means
                const float4* row4 = (const float4*)(buf + w * HWN);
                float cs = 0.f;
                #pragma unroll
                for (int k = 0; k < 7; k++) {
                    const int j = lane + 32 * k;
                    if (j < HW4) {
                        float4 v = row4[j];
                        cs += (v.x + v.y) + (v.z + v.w);
                    }
                }
                #pragma unroll
                for (int o = 16; o; o >>= 1)
                    cs += __shfl_xor_sync(0xffffffffu, cs, o);
                if (lane == 0) s_means[c * CCH + w] = cs * (1.0f / HWN);
            }
            __syncthreads();

            // all 16 warps: fold m_c * x into register s-slice
            const float* base = buf + w * SLICE + lane;
            #pragma unroll
            for (int cc = 0; cc < CCH; cc++) {
                const float  m   = s_means[c * CCH + cc];
                const float* row = base + cc * HWN;
                acc0 += m * row[0];
                if (lane < SLICE - 32) acc1 += m * row[32];
            }
        }

        // ================= stats + gate =================
        {
            float* dst = s_s + w * SLICE + lane;
            dst[0] = acc0;
            if (lane < SLICE - 32) dst[32] = acc1;
        }
        float lsum = acc0 + acc1;
        float lsq  = acc0 * acc0 + acc1 * acc1;
        #pragma unroll
        for (int o = 16; o; o >>= 1) {
            lsum += __shfl_xor_sync(0xffffffffu, lsum, o);
            lsq  += __shfl_xor_sync(0xffffffffu, lsq,  o);
        }
        if (lane == 0) { s_red[w] = lsum; s_red[NW + w] = lsq; }
        __syncthreads();
        if (tid == 0) {
            float ts = 0.f, tq = 0.f;
            #pragma unroll
            for (int i = 0; i < NW; i++) { ts += s_red[i]; tq += s_red[NW + i]; }
            const float mu  = ts * (1.0f / HWN);
            const float var = tq * (1.0f / HWN) - mu * mu;
            s_red[32] = mu;
            s_red[33] = rsqrtf(var + EPS);
        }
        __syncthreads();
        {
            const float mu = s_red[32];
            const float rs = s_red[33];
            const float wg = weight[g];
            const float bb = bias[g];
            if (tid < HW4) {
                float4 sv = s_s4[tid];
                float4 gt;
                gt.x = 1.0f / (1.0f + __expf(-((sv.x - mu) * rs * wg + bb)));
                gt.y = 1.0f / (1.0f + __expf(-((sv.y - mu) * rs * wg + bb)));
                gt.z = 1.0f / (1.0f + __expf(-((sv.z - mu) * rs * wg + bb)));
                gt.w = 1.0f / (1.0f + __expf(-((sv.w - mu) * rs * wg + bb)));
                s_s4[tid] = gt;
            }
        }
        __syncthreads();

        // ================= Phase 2: in-place multiply + TMA store,
        //                   interleaved loads of next tile =================
        const bool  hn = (tile + GRID) < NTILE;
        const char* xn = (const char*)(x + (size_t)(tile + GRID) * TILE_FLOATS);

        for (int c = 0; c < NCHUNK; c++) {
            float4* b4 = (float4*)(smem + c * CHUNK_FLOATS);
            {
                float4 v = b4[j1];
                const float4 gt = s_s4[hw1];
                v.x *= gt.x; v.y *= gt.y; v.z *= gt.z; v.w *= gt.w;
                b4[j1] = v;
            }
            if (p2b) {
                float4 v = b4[j2];
                const float4 gt = s_s4[hw2];
                v.x *= gt.x; v.y *= gt.y; v.z *= gt.z; v.w *= gt.w;
                b4[j2] = v;
            }
            __syncthreads();
            if (tid == 0) {
                asm volatile("fence.proxy.async.shared::cta;" ::: "memory");
                tma_store_chunk((char*)ot + c * CHUNK_BYTES,
                                sx0 + c * CHUNK_BYTES);
                if (hn && c >= 2) {
                    asm volatile("cp.async.bulk.wait_group.read 2;" ::: "memory");
                    tma_load_chunk(mbar0 + (c - 2) * 8,
                                   sx0 + (c - 2) * CHUNK_BYTES,
                                   xn + (c - 2) * CHUNK_BYTES);
                }
            }
        }
        if (tid == 0 && hn) {
            asm volatile("cp.async.bulk.wait_group.read 1;" ::: "memory");
            tma_load_chunk(mbar0 + 14 * 8, sx0 + 14 * CHUNK_BYTES,
                           xn + 14 * CHUNK_BYTES);
            asm volatile("cp.async.bulk.wait_group.read 0;" ::: "memory");
            tma_load_chunk(mbar0 + 15 * 8, sx0 + 15 * CHUNK_BYTES,
                           xn + 15 * CHUNK_BYTES);
        }
    }

    // drain outstanding bulk stores before exit
    if (tid == 0) {
        asm volatile("cp.async.bulk.wait_group 0;" ::: "memory");
    }
}

extern "C" void kernel_launch(void* const* d_in, const int* in_sizes, int n_in,
                              void* d_out, int out_size)
{
    const float* x  = (const float*)d_in[0];
    const float* wt = (const float*)d_in[1];
    const float* bs = (const float*)d_in[2];
    float* out = (float*)d_out;

    cudaFuncSetAttribute(simam_persist_kernel,
                         cudaFuncAttributeMaxDynamicSharedMemorySize, SMEM_BYTES);
    simam_persist_kernel<<<GRID, NTHR, SMEM_BYTES>>>(x, wt, bs, out);
}